// round 6
// baseline (speedup 1.0000x reference)
#include <cuda_runtime.h>

// DendriticLayer: B=512, N_IN=1024, N_OUT=256, T=100, dt=1.
// CONN block-diagonal (4 inputs/output) -> per-(b,o) scalar recurrence.
//   u_t = (0.9/d) u_{t-1} + C_t,  C_t = sum_j c_j [t >= e_j],  e_j = ceil(s_j)
//   exp(2 v_t) = exp2(u_t * K2 * d^t)
// R6: time-split x2. Thread parity p handles timesteps t = 2k+p via
//   u_t = rd^2 u_{t-2} + (rd*C_{t-1} + C_t)
// Parity folded into registers (no divergence): Q_j = p - e_j, c~_j = c_j d^p,
// WS uses immediate 2k with p*S correction in epilogue.

#define NPAIR 50   // 50 thread-steps x 2 timesteps = 100

__device__ __forceinline__ float ex2(float x) {
    float y;
    asm("ex2.approx.ftz.f32 %0, %1;" : "=f"(y) : "f"(x));
    return y;
}

__host__ __device__ constexpr double cpow(double b, int n) {
    return n == 0 ? 1.0 : b * cpow(b, n - 1);
}

constexpr double D1  = 0.81873075307798185867;  // exp(-0.2)
constexpr double RD  = 0.9 / D1;                // (1-a)/d
constexpr double RD2 = RD * RD;
constexpr double K2  = 2.8853900817779268147;   // 2*log2(e)

struct St {
    float Q0, Q1, Q2, Q3;     // p - ceil(s_j)
    float c0, c1, c2, c3;     // 0.1 * d^p * w_j * exp(s_j/5)
    float r0, r1, r2, r3;     // rd * c_j
    float u, S, WS;
};

template <int K>
__device__ __forceinline__ void steps(St& st) {
    if constexpr (K < NPAIR) {
        constexpr float t0 = (float)(2 * K);       // imm for [t-1 >= e]
        constexpr float t1 = (float)(2 * K + 1);   // imm for [t   >= e]
        constexpr float Et = (float)(K2 * cpow(D1, 2 * K));
        constexpr float r2 = (float)RD2;

        // indicators for both covered timesteps (FADD.SAT, imm operand)
        const float a0 = __saturatef(t0 + st.Q0);
        const float b0 = __saturatef(t1 + st.Q0);
        const float a1 = __saturatef(t0 + st.Q1);
        const float b1 = __saturatef(t1 + st.Q1);
        const float a2 = __saturatef(t0 + st.Q2);
        const float b2 = __saturatef(t1 + st.Q2);
        const float a3 = __saturatef(t0 + st.Q3);
        const float b3 = __saturatef(t1 + st.Q3);

        float D = a0 * st.r0;        // D = rd*C_{t-1} + C_t
        D = fmaf(b0, st.c0, D);
        D = fmaf(a1, st.r1, D);
        D = fmaf(b1, st.c1, D);
        D = fmaf(a2, st.r2, D);
        D = fmaf(b2, st.c2, D);
        D = fmaf(a3, st.r3, D);
        D = fmaf(b3, st.c3, D);

        st.u = fmaf(st.u, r2, D);          // u_t = rd^2 u_{t-2} + D
        const float e = ex2(st.u * Et);    // exp(2 v_t)
        st.S += e;
        st.WS = fmaf(e, t0, st.WS);        // t = 2k (+p corrected at end)

        steps<K + 1>(st);
    }
}

__global__ __launch_bounds__(128)
void dendritic_kernel(const float* __restrict__ spikes,  // [512,1024]
                      const float* __restrict__ W,       // [256,1024]
                      float* __restrict__ out)           // [512,256]
{
    const int gid  = blockIdx.x * blockDim.x + threadIdx.x;
    const int lane = threadIdx.x & 31;
    const int p    = lane >> 4;                     // parity: half-warp split
    const int sub  = lane & 15;
    const int elem = ((gid >> 5) << 4) + sub;       // b*256 + o
    const int o    = elem & 255;

    // coalesced: lanes 0-15 read 16 consecutive float4s; lanes 16-31 re-read (L1)
    const float4 s4 = reinterpret_cast<const float4*>(spikes)[elem];
    const float4 w4 = reinterpret_cast<const float4*>(W)[257 * o];

    const float pf = (float)p;
    const float dp = p ? (float)D1 : 1.0f;          // d^p folded into c's
    const float rdf = (float)RD;

    St st;
    st.Q0 = pf - ceilf(s4.x);
    st.Q1 = pf - ceilf(s4.y);
    st.Q2 = pf - ceilf(s4.z);
    st.Q3 = pf - ceilf(s4.w);
    const float k = 0.1f * dp;
    st.c0 = k * w4.x * __expf(0.2f * s4.x);
    st.c1 = k * w4.y * __expf(0.2f * s4.y);
    st.c2 = k * w4.z * __expf(0.2f * s4.z);
    st.c3 = k * w4.w * __expf(0.2f * s4.w);
    st.r0 = rdf * st.c0;
    st.r1 = rdf * st.c1;
    st.r2 = rdf * st.c2;
    st.r3 = rdf * st.c3;
    st.u = 0.0f; st.S = 0.0f; st.WS = 0.0f;

    steps<0>(st);

    // true WS for this parity: sum e*(2k+p) = WS + p*S
    const float WSt = fmaf(pf, st.S, st.WS);
    const float So  = __shfl_xor_sync(0xffffffffu, st.S, 16);
    const float Wo  = __shfl_xor_sync(0xffffffffu, WSt, 16);
    const float res = (WSt + Wo) / (st.S + So);

    if (p == 0) out[elem] = res;
}

extern "C" void kernel_launch(void* const* d_in, const int* in_sizes, int n_in,
                              void* d_out, int out_size)
{
    const float* spikes = (const float*)d_in[0];  // [512*1024]
    const float* W      = (const float*)d_in[1];  // [256*1024]
    float* out          = (float*)d_out;          // [512*256]

    // 131072 elements x 2 threads = 262144 threads = 2048 blocks x 128
    dendritic_kernel<<<2048, 128>>>(spikes, W, out);
}

// round 7
// speedup vs baseline: 1.3459x; 1.3459x over previous
#include <cuda_runtime.h>

// DendriticLayer: B=512, N_IN=1024, N_OUT=256, T=100, dt=1.
// CONN block-diagonal (4 inputs/output) -> per-(b,o) scalar recurrence.
//   u_t = (0.9/d) u_{t-1} + C_t,  C_t = sum_j c_j * ind_j(t)
//   ind_j(t) = sat(t + 1 - ceil(s_j))   (exact 0/1 at integer t)
//   exp(2 v_t) = exp2(u_t * E_t),  E_t = 2*log2(e)*d^t  (compile-time constant)
//   out = (sum_t t e_t)/(sum_t e_t)
//
// R7 = R3 structure + fused saturating add via PTX add.rn.sat.f32 (single
// FADD.SAT in SASS) instead of __saturatef(add) which lowers to FADD + F2F.SAT.

#define NSTEPS 100

__device__ __forceinline__ float ex2(float x) {
    float y;
    asm("ex2.approx.ftz.f32 %0, %1;" : "=f"(y) : "f"(x));
    return y;
}

__device__ __forceinline__ float add_sat(float a, float b) {
    float y;
    asm("add.rn.sat.f32 %0, %1, %2;" : "=f"(y) : "f"(a), "f"(b));
    return y;
}

__host__ __device__ constexpr double cpow(double b, int n) {
    return n == 0 ? 1.0 : b * cpow(b, n - 1);
}

constexpr double D1 = 0.81873075307798185867;   // exp(-0.2)
constexpr double RD = 0.9 / D1;                 // (1-a)/d
constexpr double K2 = 2.8853900817779268147;    // 2*log2(e)

struct St {
    float q0, q1, q2, q3;   // 1 - ceil(s_j)
    float c0, c1, c2, c3;   // 0.1 * w_j * exp(s_j/5)
    float u, S, WS;
};

template <int T>
__device__ __forceinline__ void steps(St& st) {
    if constexpr (T < NSTEPS) {
        constexpr float tf  = (float)T;
        constexpr float Et  = (float)(K2 * cpow(D1, T));
        constexpr float rdf = (float)RD;

        // single FADD.SAT each (exact 0/1 indicator at integer t)
        const float i0 = add_sat(tf, st.q0);
        const float i1 = add_sat(tf, st.q1);
        const float i2 = add_sat(tf, st.q2);
        const float i3 = add_sat(tf, st.q3);

        float Cp = i0 * st.c0;
        Cp = fmaf(i1, st.c1, Cp);
        Cp = fmaf(i2, st.c2, Cp);
        Cp = fmaf(i3, st.c3, Cp);

        st.u = fmaf(st.u, rdf, Cp);      // FFMA
        const float e = ex2(st.u * Et);  // FMUL-imm + MUFU.EX2
        st.S += e;                       // FADD
        st.WS = fmaf(e, tf, st.WS);      // FFMA-imm

        steps<T + 1>(st);
    }
}

__global__ __launch_bounds__(128)
void dendritic_kernel(const float* __restrict__ spikes,  // [512,1024]
                      const float* __restrict__ W,       // [256,1024]
                      float* __restrict__ out)           // [512,256]
{
    const int idx = blockIdx.x * blockDim.x + threadIdx.x;  // b*256 + o
    const int o   = idx & 255;

    // spikes[b*1024 + 4o..4o+3] -> float4 index = idx (coalesced)
    const float4 s4 = reinterpret_cast<const float4*>(spikes)[idx];
    // W[o*1024 + 4o..4o+3] -> float4 index 257*o (L1-resident)
    const float4 w4 = reinterpret_cast<const float4*>(W)[257 * o];

    St st;
    st.q0 = 1.0f - ceilf(s4.x);
    st.q1 = 1.0f - ceilf(s4.y);
    st.q2 = 1.0f - ceilf(s4.z);
    st.q3 = 1.0f - ceilf(s4.w);
    st.c0 = 0.1f * w4.x * __expf(0.2f * s4.x);
    st.c1 = 0.1f * w4.y * __expf(0.2f * s4.y);
    st.c2 = 0.1f * w4.z * __expf(0.2f * s4.z);
    st.c3 = 0.1f * w4.w * __expf(0.2f * s4.w);
    st.u = 0.0f;
    st.S = 0.0f;
    st.WS = 0.0f;

    steps<0>(st);

    out[idx] = st.WS / st.S;
}

extern "C" void kernel_launch(void* const* d_in, const int* in_sizes, int n_in,
                              void* d_out, int out_size)
{
    const float* spikes = (const float*)d_in[0];  // [512*1024]
    const float* W      = (const float*)d_in[1];  // [256*1024]
    float* out          = (float*)d_out;          // [512*256]

    dendritic_kernel<<<1024, 128>>>(spikes, W, out);
}

// round 8
// speedup vs baseline: 1.7022x; 1.2647x over previous
#include <cuda_runtime.h>

// DendriticLayer: B=512, N_IN=1024, N_OUT=256, T=100, dt=1.
// CONN block-diagonal (4 inputs/output) -> per-(b,o) scalar recurrence.
//
// R8: event-scatter formulation. All step-function logic moves out of the loop:
//   dhat[e_j] += chat_j   (per-thread private SMEM column, scattered once)
//   Chat_t = d*Chat_{t-1} + dhat_t      (Chat = K2*0.1*d^t*... bounded O(1))
//   w_t    = 0.9*w_{t-1} + Chat_t       (w = K2*v = 2*log2(e)*v, in [0,~17])
//   e_t    = exp2(w_t) = exp(2 v_t)
//   out    = (sum t*e_t)/(sum e_t)
// 6 instrs/step: LDS, FFMA-imm, FFMA-imm, MUFU.EX2, FADD, FFMA-imm.
// Two 50-step phases so the delta table fits 25.6KB/block (single wave).
// Column [t][tid] is thread-private -> conflict-free, no __syncthreads.

#define PHASE 50

__device__ __forceinline__ float ex2(float x) {
    float y;
    asm("ex2.approx.ftz.f32 %0, %1;" : "=f"(y) : "f"(x));
    return y;
}

constexpr float D1f  = 0.81873075307798185867f;  // exp(-0.2)
constexpr float K2f  = 2.8853900817779268147f;   // 2*log2(e)

struct Acc { float C, w, S, WS; };

template <int T0, int K>
__device__ __forceinline__ void steps(Acc& a, const float* __restrict__ col) {
    if constexpr (K < PHASE) {
        constexpr float tf = (float)(T0 + K);
        const float dlt = col[K * 128];          // LDS (conflict-free)
        a.C = fmaf(a.C, D1f, dlt);               // Chat = d*Chat + delta
        a.w = fmaf(a.w, 0.9f, a.C);              // w = 0.9w + Chat
        const float e = ex2(a.w);
        a.S += e;
        a.WS = fmaf(e, tf, a.WS);
        steps<T0, K + 1>(a, col);
    }
}

__global__ __launch_bounds__(128)
void dendritic_kernel(const float* __restrict__ spikes,  // [512,1024]
                      const float* __restrict__ W,       // [256,1024]
                      float* __restrict__ out)           // [512,256]
{
    __shared__ float tbl[PHASE * 128];           // [t][tid] : 25.6KB

    const int tid = threadIdx.x;
    const int idx = blockIdx.x * 128 + tid;      // b*256 + o
    const int o   = idx & 255;

    // coalesced float4 loads (see R3 derivation)
    const float4 s4 = reinterpret_cast<const float4*>(spikes)[idx];
    const float4 w4 = reinterpret_cast<const float4*>(W)[257 * o];

    // event times and injected amplitudes (all O(1))
    const float e0 = ceilf(s4.x), e1 = ceilf(s4.y), e2 = ceilf(s4.z), e3 = ceilf(s4.w);
    const float kk = 0.1f * K2f;
    const float c0 = kk * w4.x * __expf(0.2f * (s4.x - e0));
    const float c1 = kk * w4.y * __expf(0.2f * (s4.y - e1));
    const float c2 = kk * w4.z * __expf(0.2f * (s4.z - e2));
    const float c3 = kk * w4.w * __expf(0.2f * (s4.w - e3));
    const int i0 = (int)e0, i1 = (int)e1, i2 = (int)e2, i3 = (int)e3;

    float* col = tbl + tid;
    Acc a; a.C = 0.0f; a.w = 0.0f; a.S = 0.0f; a.WS = 0.0f;

    // ---- phase 0: t in [0,50) ----
    #pragma unroll
    for (int k = 0; k < PHASE; ++k) col[k * 128] = 0.0f;
    if (i0 < 50) col[i0 * 128] += c0;            // private column: no races
    if (i1 < 50) col[i1 * 128] += c1;
    if (i2 < 50) col[i2 * 128] += c2;
    if (i3 < 50) col[i3 * 128] += c3;
    steps<0, 0>(a, col);

    // ---- phase 1: t in [50,100) ----
    #pragma unroll
    for (int k = 0; k < PHASE; ++k) col[k * 128] = 0.0f;
    if (i0 >= 50 && i0 < 100) col[(i0 - 50) * 128] += c0;
    if (i1 >= 50 && i1 < 100) col[(i1 - 50) * 128] += c1;
    if (i2 >= 50 && i2 < 100) col[(i2 - 50) * 128] += c2;
    if (i3 >= 50 && i3 < 100) col[(i3 - 50) * 128] += c3;
    steps<50, 0>(a, col);

    out[idx] = a.WS / a.S;
}

extern "C" void kernel_launch(void* const* d_in, const int* in_sizes, int n_in,
                              void* d_out, int out_size)
{
    const float* spikes = (const float*)d_in[0];  // [512*1024]
    const float* W      = (const float*)d_in[1];  // [256*1024]
    float* out          = (float*)d_out;          // [512*256]

    dendritic_kernel<<<1024, 128>>>(spikes, W, out);
}

// round 9
// speedup vs baseline: 1.7085x; 1.0037x over previous
#include <cuda_runtime.h>

// DendriticLayer: B=512, N_IN=1024, N_OUT=256, T=100, dt=1.
// CONN block-diagonal (4 inputs/output) -> per-(b,o) scalar recurrence.
//
// Event-scatter formulation (R8) + 4x-vectorized delta table (R9):
//   delta[e_j] += chat_j,  chat_j = 0.1*K2*w_j*exp((s_j-ceil(s_j))/5)
//   Chat_t = d*Chat_{t-1} + delta_t
//   w_t    = 0.9*w_{t-1} + Chat_t          (w = 2*log2(e)*v)
//   e_t    = exp2(w_t);  out = (sum t*e_t)/(sum e_t)
// Table layout: float4 tbl[chunk][tid] -> one LDS.128 serves 4 timesteps
// (conflict-free: thread i covers banks 4i..4i+3, 4 phases = inherent floor).
// Two phases (52 + 48 steps) keep SMEM at 26.6KB -> full occupancy wave.
// Columns are thread-private: no atomics, no __syncthreads.

#define CH0 13   // phase-0 chunks: 52 steps (t in [0,52))
#define CH1 12   // phase-1 chunks: 48 steps (t in [52,100))

__device__ __forceinline__ float ex2(float x) {
    float y;
    asm("ex2.approx.ftz.f32 %0, %1;" : "=f"(y) : "f"(x));
    return y;
}

constexpr float D1f = 0.81873075307798185867f;  // exp(-0.2)
constexpr float K2f = 2.8853900817779268147f;   // 2*log2(e)

struct Acc { float C, w, S, WS; };

__device__ __forceinline__ void step(Acc& a, float dlt, float tf) {
    a.C = fmaf(a.C, D1f, dlt);    // FFMA-imm
    a.w = fmaf(a.w, 0.9f, a.C);   // FFMA-imm
    const float e = ex2(a.w);     // MUFU.EX2
    a.S += e;                     // FADD
    a.WS = fmaf(e, tf, a.WS);     // FFMA-imm (tf is a compile-time literal)
}

template <int T0, int NCH, int K>
__device__ __forceinline__ void run(Acc& a, const float4* __restrict__ col) {
    if constexpr (K < NCH) {
        const float4 d4 = col[K * 128];          // LDS.128: 4 steps of deltas
        step(a, d4.x, (float)(T0 + 4 * K + 0));
        step(a, d4.y, (float)(T0 + 4 * K + 1));
        step(a, d4.z, (float)(T0 + 4 * K + 2));
        step(a, d4.w, (float)(T0 + 4 * K + 3));
        run<T0, NCH, K + 1>(a, col);
    }
}

__global__ __launch_bounds__(128)
void dendritic_kernel(const float* __restrict__ spikes,  // [512,1024]
                      const float* __restrict__ W,       // [256,1024]
                      float* __restrict__ out)           // [512,256]
{
    __shared__ float4 tbl[CH0][128];             // 26.6KB

    const int tid = threadIdx.x;
    const int idx = blockIdx.x * 128 + tid;      // b*256 + o
    const int o   = idx & 255;

    const float4 s4 = reinterpret_cast<const float4*>(spikes)[idx];
    const float4 w4 = reinterpret_cast<const float4*>(W)[257 * o];

    const float e0 = ceilf(s4.x), e1 = ceilf(s4.y), e2 = ceilf(s4.z), e3 = ceilf(s4.w);
    const float kk = 0.1f * K2f;
    const float c0 = kk * w4.x * __expf(0.2f * (s4.x - e0));
    const float c1 = kk * w4.y * __expf(0.2f * (s4.y - e1));
    const float c2 = kk * w4.z * __expf(0.2f * (s4.z - e2));
    const float c3 = kk * w4.w * __expf(0.2f * (s4.w - e3));
    const int i0 = (int)e0, i1 = (int)e1, i2 = (int)e2, i3 = (int)e3;

    float* tf = reinterpret_cast<float*>(tbl);
    const int tb = tid * 4;
    // scalar slot for timestep k (local to a phase): (k>>2)*512 + tid*4 + (k&3)
    #define SLOT(k) (((k) >> 2) * 512 + tb + ((k) & 3))

    const float4* col = &tbl[0][tid];
    float4 z4 = make_float4(0.f, 0.f, 0.f, 0.f);
    Acc a; a.C = 0.f; a.w = 0.f; a.S = 0.f; a.WS = 0.f;

    // ---- phase 0: t in [0,52) ----
    #pragma unroll
    for (int c = 0; c < CH0; ++c) tbl[c][tid] = z4;       // 13x STS.128
    if (i0 < 52) tf[SLOT(i0)] += c0;                       // private RMW
    if (i1 < 52) tf[SLOT(i1)] += c1;
    if (i2 < 52) tf[SLOT(i2)] += c2;
    if (i3 < 52) tf[SLOT(i3)] += c3;
    run<0, CH0, 0>(a, col);

    // ---- phase 1: t in [52,100) ----
    #pragma unroll
    for (int c = 0; c < CH1; ++c) tbl[c][tid] = z4;       // 12x STS.128
    if (i0 >= 52 && i0 < 100) tf[SLOT(i0 - 52)] += c0;
    if (i1 >= 52 && i1 < 100) tf[SLOT(i1 - 52)] += c1;
    if (i2 >= 52 && i2 < 100) tf[SLOT(i2 - 52)] += c2;
    if (i3 >= 52 && i3 < 100) tf[SLOT(i3 - 52)] += c3;
    run<52, CH1, 0>(a, col);

    out[idx] = a.WS / a.S;
}

extern "C" void kernel_launch(void* const* d_in, const int* in_sizes, int n_in,
                              void* d_out, int out_size)
{
    const float* spikes = (const float*)d_in[0];  // [512*1024]
    const float* W      = (const float*)d_in[1];  // [256*1024]
    float* out          = (float*)d_out;          // [512*256]

    dendritic_kernel<<<1024, 128>>>(spikes, W, out);
}